// round 8
// baseline (speedup 1.0000x reference)
#include <cuda_runtime.h>
#include <cstddef>

#define BB 256
#define TT 2048
#define NXX 64
#define NUU 32
#define NYY 16
#define HH 128

// Named barriers: A = recurrence warps only (256 thr), B = whole CTA (288 thr).
#define BAR_A() asm volatile("bar.sync 1, 256;" ::: "memory")
#define BAR_B() asm volatile("bar.sync 2, 288;" ::: "memory")

// IEEE round-to-nearest divide, immune to fast-math substitution.
__device__ __forceinline__ float fdiv_rn(float a, float b) {
    float r; asm("div.rn.f32 %0, %1, %2;" : "=f"(r) : "f"(a), "f"(b)); return r;
}

// Exact replication of XLA EmitFastTanh (FMA-capable target). DO NOT TOUCH.
__device__ __forceinline__ float xla_tanh(float x) {
    const float kClamp = 7.99881172180175781f;
    float xc = fmaxf(-kClamp, fminf(x, kClamp));
    float x2 = __fmul_rn(xc, xc);
    float p = fmaf(x2, -2.76076847742355e-16f, 2.00018790482477e-13f);
    p = fmaf(x2, p, -8.60467152213735e-11f);
    p = fmaf(x2, p,  5.12229709037114e-08f);
    p = fmaf(x2, p,  1.48572235717979e-05f);
    p = fmaf(x2, p,  6.37261928875436e-04f);
    p = fmaf(x2, p,  4.89352455891786e-03f);
    float num = __fmul_rn(xc, p);
    float q = fmaf(x2, 1.19825839466702e-06f, 1.18534705686654e-04f);
    q = fmaf(x2, q, 2.26843463243900e-03f);
    q = fmaf(x2, q, 4.89352518554385e-03f);
    float r = fdiv_rn(num, q);
    return (fabsf(x) < 0.0004f) ? x : r;
}

// 128 CTAs x 288 threads; 2 batch elements per CTA.
//   tid   0..127 : GEMV1. Phase 1: zg chains -> g1s. Phase 2: zh -> h1p.
//   tid 128..255 : dx. Phase 1: out_x STG + u(t+2) LDG. Phase 2: 128-dot + update.
//   tid 256..287 : y. After barrier B(t): compute y(t) from h1p[t&1], store;
//                  overlaps the whole of step t+1 (gates nothing but B(t+1)).
// All dot orders / add orders identical to the R6/R7 passing kernel.

__global__ __launch_bounds__(288, 1)
void ssm_kernel(const float* __restrict__ x0,
                const float* __restrict__ u,
                const float* __restrict__ Wg1, const float* __restrict__ bg1,
                const float* __restrict__ Wg2, const float* __restrict__ bg2,
                const float* __restrict__ Wh1, const float* __restrict__ bh1,
                const float* __restrict__ Wh2, const float* __restrict__ bh2,
                float* __restrict__ out_x, float* __restrict__ out_y)
{
    __shared__ __align__(16) float sxu[2][2][96];   // [parity][e][0..63 x | 64..95 u]
    __shared__ __align__(16) float g1s[2][HH];      // tanh(g layer-1)
    __shared__ __align__(16) float h1p[2][2][HH];   // tanh(h layer-1), double buffer

    const int tid = threadIdx.x;
    const int b0  = blockIdx.x * 2;

    // ---- init: x0, u0 into parity-0 buffer ----
    if (tid < 128) {
        int e = tid >> 6, j = tid & 63;
        sxu[0][e][j] = x0[(size_t)(b0 + e) * NXX + j];
    } else if (tid < 192) {
        int q = tid - 128;
        int e = q >> 5, k = q & 31;
        sxu[0][e][64 + k] = u[(size_t)(b0 + e) * TT * NUU + k];
    }

    if (tid < 128) {
        // ===================== GEMV1 warps =====================
        const int h = tid;
        float wg1r[96];
        float wh1r[64];
        #pragma unroll
        for (int k = 0; k < 96; k++) wg1r[k] = Wg1[k * HH + h];
        #pragma unroll
        for (int k = 0; k < 64; k++) wh1r[k] = Wh1[k * HH + h];
        const float bg1r = bg1[h];
        const float bh1r = bh1[h];

        __syncthreads();  // init visible

        #pragma unroll 1
        for (int t = 0; t < TT; t++) {
            const int p = t & 1;
            const float4* x40 = (const float4*)&sxu[p][0][0];
            const float4* x41 = (const float4*)&sxu[p][1][0];

            // ---- phase 1: g-net layer 1 (k = 0..95 ascending) ----
            float zg0 = 0.f, zg1 = 0.f;
            #pragma unroll
            for (int k4 = 0; k4 < 24; k4++) {
                const float4 a = x40[k4];
                const float4 b = x41[k4];
                zg0 = fmaf(a.x, wg1r[4*k4+0], zg0);
                zg0 = fmaf(a.y, wg1r[4*k4+1], zg0);
                zg0 = fmaf(a.z, wg1r[4*k4+2], zg0);
                zg0 = fmaf(a.w, wg1r[4*k4+3], zg0);
                zg1 = fmaf(b.x, wg1r[4*k4+0], zg1);
                zg1 = fmaf(b.y, wg1r[4*k4+1], zg1);
                zg1 = fmaf(b.z, wg1r[4*k4+2], zg1);
                zg1 = fmaf(b.w, wg1r[4*k4+3], zg1);
            }
            g1s[0][h] = xla_tanh(__fadd_rn(zg0, bg1r));
            g1s[1][h] = xla_tanh(__fadd_rn(zg1, bg1r));
            BAR_A();  // g1 published -> dx chain may start

            // ---- phase 2 (overlaps dx chain): h-net layer 1 ----
            float zh0 = 0.f, zh1 = 0.f;
            #pragma unroll
            for (int k4 = 0; k4 < 16; k4++) {
                const float4 a = x40[k4];
                const float4 b = x41[k4];
                zh0 = fmaf(a.x, wh1r[4*k4+0], zh0);
                zh0 = fmaf(a.y, wh1r[4*k4+1], zh0);
                zh0 = fmaf(a.z, wh1r[4*k4+2], zh0);
                zh0 = fmaf(a.w, wh1r[4*k4+3], zh0);
                zh1 = fmaf(b.x, wh1r[4*k4+0], zh1);
                zh1 = fmaf(b.y, wh1r[4*k4+1], zh1);
                zh1 = fmaf(b.z, wh1r[4*k4+2], zh1);
                zh1 = fmaf(b.w, wh1r[4*k4+3], zh1);
            }
            h1p[p][0][h] = xla_tanh(__fadd_rn(zh0, bh1r));
            h1p[p][1][h] = xla_tanh(__fadd_rn(zh1, bh1r));
            BAR_B();  // state + h1 committed
        }
    } else if (tid < 256) {
        // ===================== dx warps =====================
        const int q = tid - 128;
        const int e = q >> 6;
        const int j = q & 63;

        float wg2r[128];
        #pragma unroll
        for (int i = 0; i < 128; i++) wg2r[i] = Wg2[i * NXX + j];
        const float bg2r = bg2[j];

        const int eu = q >> 5, ku = q & 31;              // u prefetch duty (q<64)
        const size_t u_base = (size_t)(b0 + eu) * TT * NUU + ku;

        float xreg = x0[(size_t)(b0 + e) * NXX + j];     // x_t in register
        float* oxp = out_x + (size_t)(b0 + e) * TT * NXX + j;

        // two-step u pipeline: u_cur holds u(t+1) at top of step t
        float u_cur = 0.0f;
        if (q < 64) u_cur = u[u_base + (size_t)((1 < TT) ? 1 : (TT - 1)) * NUU];

        __syncthreads();  // init visible

        const float4* g4 = (const float4*)&g1s[e][0];

        #pragma unroll 1
        for (int t = 0; t < TT; t++) {
            const int pn = (t + 1) & 1;

            // ---- phase 1: record x_t, launch u(t+2) load ----
            *oxp = xreg;  oxp += NXX;
            float u_next = 0.0f;
            if (q < 64) {
                int tn = (t + 2 < TT) ? (t + 2) : (TT - 1);
                u_next = u[u_base + (size_t)tn * NUU];
            }
            BAR_A();  // g1 ready

            // ---- phase 2: sequential 128-dot (ascending i) ----
            float dxa = 0.0f;
            #pragma unroll
            for (int i4 = 0; i4 < 32; i4++) {
                const float4 v = g4[i4];
                dxa = fmaf(v.x, wg2r[4*i4+0], dxa);
                dxa = fmaf(v.y, wg2r[4*i4+1], dxa);
                dxa = fmaf(v.z, wg2r[4*i4+2], dxa);
                dxa = fmaf(v.w, wg2r[4*i4+3], dxa);
            }
            // pinned HLO order: x_{t+1} = x + (dot + bg2)
            xreg = __fadd_rn(xreg, __fadd_rn(dxa, bg2r));
            sxu[pn][e][j] = xreg;
            if (q < 64) sxu[pn][eu][64 + ku] = u_cur;    // u(t+1), loaded 1 step ago
            u_cur = u_next;
            BAR_B();
        }
    } else {
        // ===================== y warp (lagged, off the gate) =====================
        const int o  = tid - 256;       // 0..31
        const int e  = o >> 4;
        const int oo = o & 15;

        float wh2r[128];
        #pragma unroll
        for (int i = 0; i < 128; i++) wh2r[i] = Wh2[i * NYY + oo];
        const float bh2r = bh2[oo];

        float* oyp = out_y + (size_t)(b0 + e) * TT * NYY + oo;

        __syncthreads();  // init visible

        #pragma unroll 1
        for (int t = 0; t < TT; t++) {
            BAR_B();  // B(t): h1p[t&1] is ready
            const int pp = t & 1;
            const float4* h4 = (const float4*)&h1p[pp][e][0];
            float ya = 0.0f;
            #pragma unroll
            for (int i4 = 0; i4 < 32; i4++) {
                const float4 v = h4[i4];
                ya = fmaf(v.x, wh2r[4*i4+0], ya);
                ya = fmaf(v.y, wh2r[4*i4+1], ya);
                ya = fmaf(v.z, wh2r[4*i4+2], ya);
                ya = fmaf(v.w, wh2r[4*i4+3], ya);
            }
            *oyp = __fadd_rn(ya, bh2r);  oyp += NYY;
        }
    }
}

extern "C" void kernel_launch(void* const* d_in, const int* in_sizes, int n_in,
                              void* d_out, int out_size)
{
    const float* x0  = (const float*)d_in[0];
    const float* u   = (const float*)d_in[1];
    const float* Wg1 = (const float*)d_in[2];
    const float* bg1 = (const float*)d_in[3];
    const float* Wg2 = (const float*)d_in[4];
    const float* bg2 = (const float*)d_in[5];
    const float* Wh1 = (const float*)d_in[6];
    const float* bh1 = (const float*)d_in[7];
    const float* Wh2 = (const float*)d_in[8];
    const float* bh2 = (const float*)d_in[9];

    float* out_x = (float*)d_out;
    float* out_y = out_x + (size_t)BB * TT * NXX;

    ssm_kernel<<<BB / 2, 288>>>(x0, u, Wg1, bg1, Wg2, bg2,
                                Wh1, bh1, Wh2, bh2, out_x, out_y);
}

// round 9
// speedup vs baseline: 1.4520x; 1.4520x over previous
#include <cuda_runtime.h>
#include <cstddef>

#define BB 256
#define TT 2048
#define NXX 64
#define NUU 32
#define NYY 16
#define HH 128

// BAR_A: g-warps + dx-warps only (192 threads). B: full CTA __syncthreads (352).
#define BAR_A() asm volatile("bar.sync 1, 192;" ::: "memory")

// IEEE round-to-nearest divide, immune to fast-math substitution.
__device__ __forceinline__ float fdiv_rn(float a, float b) {
    float r; asm("div.rn.f32 %0, %1, %2;" : "=f"(r) : "f"(a), "f"(b)); return r;
}

// Exact replication of XLA EmitFastTanh (FMA-capable target). DO NOT TOUCH.
__device__ __forceinline__ float xla_tanh(float x) {
    const float kClamp = 7.99881172180175781f;
    float xc = fmaxf(-kClamp, fminf(x, kClamp));
    float x2 = __fmul_rn(xc, xc);
    float p = fmaf(x2, -2.76076847742355e-16f, 2.00018790482477e-13f);
    p = fmaf(x2, p, -8.60467152213735e-11f);
    p = fmaf(x2, p,  5.12229709037114e-08f);
    p = fmaf(x2, p,  1.48572235717979e-05f);
    p = fmaf(x2, p,  6.37261928875436e-04f);
    p = fmaf(x2, p,  4.89352455891786e-03f);
    float num = __fmul_rn(xc, p);
    float q = fmaf(x2, 1.19825839466702e-06f, 1.18534705686654e-04f);
    q = fmaf(x2, q, 2.26843463243900e-03f);
    q = fmaf(x2, q, 4.89352518554385e-03f);
    float r = fdiv_rn(num, q);
    return (fabsf(x) < 0.0004f) ? x : r;
}

// 128 CTAs x 352 threads; 2 batch elements per CTA.
//   tid   0..127 : g-warps.  Phase1: zg chains (96 weight regs) -> g1s. BAR_A, then idle to B.
//   tid 128..191 : dx-warps. Phase1: out_x STG + u LDG. BAR_A. Phase2: two 128-dots, update x.
//   tid 192..319 : h-warps.  Whole step: zh chains -> h1p[parity]. Join B only.
//   tid 320..351 : y-warp.   After B(t): y(t) from h1p[t&1]. Off the gated path.
// All accumulation orders identical to the passing R6/R7/R8 kernels.

__global__ __launch_bounds__(352, 1)
void ssm_kernel(const float* __restrict__ x0,
                const float* __restrict__ u,
                const float* __restrict__ Wg1, const float* __restrict__ bg1,
                const float* __restrict__ Wg2, const float* __restrict__ bg2,
                const float* __restrict__ Wh1, const float* __restrict__ bh1,
                const float* __restrict__ Wh2, const float* __restrict__ bh2,
                float* __restrict__ out_x, float* __restrict__ out_y)
{
    __shared__ __align__(16) float sxu[2][2][96];   // [parity][e][0..63 x | 64..95 u]
    __shared__ __align__(16) float g1s[2][HH];      // tanh(g layer-1)
    __shared__ __align__(16) float h1p[2][2][HH];   // tanh(h layer-1), double buffer

    const int tid = threadIdx.x;
    const int b0  = blockIdx.x * 2;

    // ---- init: x0, u0 into parity-0 buffer ----
    if (tid < 128) {
        int e = tid >> 6, j = tid & 63;
        sxu[0][e][j] = x0[(size_t)(b0 + e) * NXX + j];
    } else if (tid < 192) {
        int q = tid - 128;
        int e = q >> 5, k = q & 31;
        sxu[0][e][64 + k] = u[(size_t)(b0 + e) * TT * NUU + k];
    }

    if (tid < 128) {
        // ===================== g-warps =====================
        const int h = tid;
        float wg1r[96];
        #pragma unroll
        for (int k = 0; k < 96; k++) wg1r[k] = Wg1[k * HH + h];
        const float bg1r = bg1[h];

        __syncthreads();  // init visible

        #pragma unroll 1
        for (int t = 0; t < TT; t++) {
            const int p = t & 1;
            const float4* x40 = (const float4*)&sxu[p][0][0];
            const float4* x41 = (const float4*)&sxu[p][1][0];

            float zg0 = 0.f, zg1 = 0.f;
            #pragma unroll
            for (int k4 = 0; k4 < 24; k4++) {
                const float4 a = x40[k4];
                const float4 b = x41[k4];
                zg0 = fmaf(a.x, wg1r[4*k4+0], zg0);
                zg0 = fmaf(a.y, wg1r[4*k4+1], zg0);
                zg0 = fmaf(a.z, wg1r[4*k4+2], zg0);
                zg0 = fmaf(a.w, wg1r[4*k4+3], zg0);
                zg1 = fmaf(b.x, wg1r[4*k4+0], zg1);
                zg1 = fmaf(b.y, wg1r[4*k4+1], zg1);
                zg1 = fmaf(b.z, wg1r[4*k4+2], zg1);
                zg1 = fmaf(b.w, wg1r[4*k4+3], zg1);
            }
            g1s[0][h] = xla_tanh(__fadd_rn(zg0, bg1r));
            g1s[1][h] = xla_tanh(__fadd_rn(zg1, bg1r));
            BAR_A();          // g1 published -> dx chain starts
            __syncthreads();  // B
        }
    } else if (tid < 192) {
        // ===================== dx-warps (one column j, both elements) ============
        const int q = tid - 128;        // 0..63
        const int j = q;

        float wg2r[128];
        #pragma unroll
        for (int i = 0; i < 128; i++) wg2r[i] = Wg2[i * NXX + j];
        const float bg2r = bg2[j];

        const int eu = q >> 5, ku = q & 31;              // u prefetch duty (all 64)
        const size_t u_base = (size_t)(b0 + eu) * TT * NUU + ku;

        float xr0 = x0[(size_t)(b0 + 0) * NXX + j];
        float xr1 = x0[(size_t)(b0 + 1) * NXX + j];
        float* oxp0 = out_x + (size_t)(b0 + 0) * TT * NXX + j;
        float* oxp1 = out_x + (size_t)(b0 + 1) * TT * NXX + j;

        __syncthreads();  // init visible

        const float4* g40 = (const float4*)&g1s[0][0];
        const float4* g41 = (const float4*)&g1s[1][0];

        #pragma unroll 1
        for (int t = 0; t < TT; t++) {
            const int pn = (t + 1) & 1;

            // ---- phase 1: record x_t, launch u(t+1) load ----
            *oxp0 = xr0;  oxp0 += NXX;
            *oxp1 = xr1;  oxp1 += NXX;
            int tn = (t + 1 < TT) ? (t + 1) : (TT - 1);
            float un = u[u_base + (size_t)tn * NUU];
            BAR_A();  // g1 ready

            // ---- phase 2: two sequential 128-dots (ascending i) ----
            float dxa0 = 0.0f, dxa1 = 0.0f;
            #pragma unroll
            for (int i4 = 0; i4 < 32; i4++) {
                const float4 v0 = g40[i4];
                const float4 v1 = g41[i4];
                dxa0 = fmaf(v0.x, wg2r[4*i4+0], dxa0);
                dxa0 = fmaf(v0.y, wg2r[4*i4+1], dxa0);
                dxa0 = fmaf(v0.z, wg2r[4*i4+2], dxa0);
                dxa0 = fmaf(v0.w, wg2r[4*i4+3], dxa0);
                dxa1 = fmaf(v1.x, wg2r[4*i4+0], dxa1);
                dxa1 = fmaf(v1.y, wg2r[4*i4+1], dxa1);
                dxa1 = fmaf(v1.z, wg2r[4*i4+2], dxa1);
                dxa1 = fmaf(v1.w, wg2r[4*i4+3], dxa1);
            }
            // pinned HLO order: x_{t+1} = x + (dot + bg2)
            xr0 = __fadd_rn(xr0, __fadd_rn(dxa0, bg2r));
            xr1 = __fadd_rn(xr1, __fadd_rn(dxa1, bg2r));
            sxu[pn][0][j] = xr0;
            sxu[pn][1][j] = xr1;
            sxu[pn][eu][64 + ku] = un;
            __syncthreads();  // B
        }
    } else if (tid < 320) {
        // ===================== h-warps (whole-step slack, B only) =================
        const int h = tid - 192;        // 0..127
        float wh1r[64];
        #pragma unroll
        for (int k = 0; k < 64; k++) wh1r[k] = Wh1[k * HH + h];
        const float bh1r = bh1[h];

        __syncthreads();  // init visible

        #pragma unroll 1
        for (int t = 0; t < TT; t++) {
            const int p = t & 1;
            const float4* x40 = (const float4*)&sxu[p][0][0];
            const float4* x41 = (const float4*)&sxu[p][1][0];

            float zh0 = 0.f, zh1 = 0.f;
            #pragma unroll
            for (int k4 = 0; k4 < 16; k4++) {
                const float4 a = x40[k4];
                const float4 b = x41[k4];
                zh0 = fmaf(a.x, wh1r[4*k4+0], zh0);
                zh0 = fmaf(a.y, wh1r[4*k4+1], zh0);
                zh0 = fmaf(a.z, wh1r[4*k4+2], zh0);
                zh0 = fmaf(a.w, wh1r[4*k4+3], zh0);
                zh1 = fmaf(b.x, wh1r[4*k4+0], zh1);
                zh1 = fmaf(b.y, wh1r[4*k4+1], zh1);
                zh1 = fmaf(b.z, wh1r[4*k4+2], zh1);
                zh1 = fmaf(b.w, wh1r[4*k4+3], zh1);
            }
            h1p[p][0][h] = xla_tanh(__fadd_rn(zh0, bh1r));
            h1p[p][1][h] = xla_tanh(__fadd_rn(zh1, bh1r));
            __syncthreads();  // B: h1 committed with state
        }
    } else {
        // ===================== y-warp (lagged, off the gate) ======================
        const int o  = tid - 320;       // 0..31
        const int e  = o >> 4;
        const int oo = o & 15;

        float wh2r[128];
        #pragma unroll
        for (int i = 0; i < 128; i++) wh2r[i] = Wh2[i * NYY + oo];
        const float bh2r = bh2[oo];

        float* oyp = out_y + (size_t)(b0 + e) * TT * NYY + oo;

        __syncthreads();  // init visible

        #pragma unroll 1
        for (int t = 0; t < TT; t++) {
            __syncthreads();  // B(t): h1p[t&1] ready
            const int pp = t & 1;
            const float4* h4 = (const float4*)&h1p[pp][e][0];
            float ya = 0.0f;
            #pragma unroll
            for (int i4 = 0; i4 < 32; i4++) {
                const float4 v = h4[i4];
                ya = fmaf(v.x, wh2r[4*i4+0], ya);
                ya = fmaf(v.y, wh2r[4*i4+1], ya);
                ya = fmaf(v.z, wh2r[4*i4+2], ya);
                ya = fmaf(v.w, wh2r[4*i4+3], ya);
            }
            *oyp = __fadd_rn(ya, bh2r);  oyp += NYY;
        }
    }
}

extern "C" void kernel_launch(void* const* d_in, const int* in_sizes, int n_in,
                              void* d_out, int out_size)
{
    const float* x0  = (const float*)d_in[0];
    const float* u   = (const float*)d_in[1];
    const float* Wg1 = (const float*)d_in[2];
    const float* bg1 = (const float*)d_in[3];
    const float* Wg2 = (const float*)d_in[4];
    const float* bg2 = (const float*)d_in[5];
    const float* Wh1 = (const float*)d_in[6];
    const float* bh1 = (const float*)d_in[7];
    const float* Wh2 = (const float*)d_in[8];
    const float* bh2 = (const float*)d_in[9];

    float* out_x = (float*)d_out;
    float* out_y = out_x + (size_t)BB * TT * NXX;

    ssm_kernel<<<BB / 2, 352>>>(x0, u, Wg1, bg1, Wg2, bg2,
                                Wh1, bh1, Wh2, bh2, out_x, out_y);
}

// round 10
// speedup vs baseline: 1.4770x; 1.0172x over previous
#include <cuda_runtime.h>
#include <cstddef>

#define BB 256
#define TT 2048
#define NXX 64
#define NUU 32
#define NYY 16
#define HH 128

typedef unsigned long long u64;

// BAR_A: g-warps + dx-warps only (192 threads). B: full CTA __syncthreads (352).
#define BAR_A() asm volatile("bar.sync 1, 192;" ::: "memory")

// Packed fp32x2 helpers (per-lane IEEE fma.rn, identical to scalar fma.rn.f32).
__device__ __forceinline__ u64 pk2(float lo, float hi) {
    u64 r; asm("mov.b64 %0, {%1, %2};" : "=l"(r) : "f"(lo), "f"(hi)); return r;
}
__device__ __forceinline__ void upk2(u64 v, float& lo, float& hi) {
    asm("mov.b64 {%0, %1}, %2;" : "=f"(lo), "=f"(hi) : "l"(v));
}
__device__ __forceinline__ u64 fma2(u64 a, u64 b, u64 c) {
    u64 d; asm("fma.rn.f32x2 %0, %1, %2, %3;" : "=l"(d) : "l"(a), "l"(b), "l"(c)); return d;
}

// IEEE round-to-nearest divide, immune to fast-math substitution.
__device__ __forceinline__ float fdiv_rn(float a, float b) {
    float r; asm("div.rn.f32 %0, %1, %2;" : "=f"(r) : "f"(a), "f"(b)); return r;
}

// Exact replication of XLA EmitFastTanh (FMA-capable target). DO NOT TOUCH.
__device__ __forceinline__ float xla_tanh(float x) {
    const float kClamp = 7.99881172180175781f;
    float xc = fmaxf(-kClamp, fminf(x, kClamp));
    float x2 = __fmul_rn(xc, xc);
    float p = fmaf(x2, -2.76076847742355e-16f, 2.00018790482477e-13f);
    p = fmaf(x2, p, -8.60467152213735e-11f);
    p = fmaf(x2, p,  5.12229709037114e-08f);
    p = fmaf(x2, p,  1.48572235717979e-05f);
    p = fmaf(x2, p,  6.37261928875436e-04f);
    p = fmaf(x2, p,  4.89352455891786e-03f);
    float num = __fmul_rn(xc, p);
    float q = fmaf(x2, 1.19825839466702e-06f, 1.18534705686654e-04f);
    q = fmaf(x2, q, 2.26843463243900e-03f);
    q = fmaf(x2, q, 4.89352518554385e-03f);
    float r = fdiv_rn(num, q);
    return (fabsf(x) < 0.0004f) ? x : r;
}

// 128 CTAs x 352 threads; 2 batch elements per CTA, packed lane-wise (f32x2):
// lane.lo = element 0, lane.hi = element 1, weights shared across lanes.
//   tid   0..127 : g-warps.  Phase1: packed zg chain -> g1s pairs. BAR_A.
//   tid 128..191 : dx-warps. Phase1: out_x STG + u LDG. BAR_A. Phase2: packed 128-dot.
//   tid 192..319 : h-warps.  Whole step: packed zh chain -> h1p pairs. B only.
//   tid 320..351 : y threads (16 active). After B(t): packed y(t) dot, 2 STG.
// Per-lane accumulation orders identical to R6-R9 passing kernels (bit-exact).

__global__ __launch_bounds__(352, 1)
void ssm_kernel(const float* __restrict__ x0,
                const float* __restrict__ u,
                const float* __restrict__ Wg1, const float* __restrict__ bg1,
                const float* __restrict__ Wg2, const float* __restrict__ bg2,
                const float* __restrict__ Wh1, const float* __restrict__ bh1,
                const float* __restrict__ Wh2, const float* __restrict__ bh2,
                float* __restrict__ out_x, float* __restrict__ out_y)
{
    __shared__ __align__(16) float2 sxu2[2][96];   // [parity][k] = (e0,e1); 0..63 x, 64..95 u
    __shared__ __align__(16) float2 g1s2[HH];      // tanh(g layer-1) pairs
    __shared__ __align__(16) float2 h1p2[2][HH];   // tanh(h layer-1) pairs, double buffer

    const int tid = threadIdx.x;
    const int b0  = blockIdx.x * 2;

    // ---- init: x0, u0 into parity-0 buffer as pairs ----
    if (tid < 64) {
        sxu2[0][tid] = make_float2(x0[(size_t)(b0 + 0) * NXX + tid],
                                   x0[(size_t)(b0 + 1) * NXX + tid]);
    } else if (tid >= 128 && tid < 160) {
        int k = tid - 128;
        sxu2[0][64 + k] = make_float2(u[(size_t)(b0 + 0) * TT * NUU + k],
                                      u[(size_t)(b0 + 1) * TT * NUU + k]);
    }

    if (tid < 128) {
        // ===================== g-warps =====================
        const int h = tid;
        float wg1r[96];
        #pragma unroll
        for (int k = 0; k < 96; k++) wg1r[k] = Wg1[k * HH + h];
        const float bg1r = bg1[h];

        __syncthreads();  // init visible

        #pragma unroll 1
        for (int t = 0; t < TT; t++) {
            const int p = t & 1;
            const ulonglong2* x2 = (const ulonglong2*)&sxu2[p][0];

            u64 zg = pk2(0.f, 0.f);
            #pragma unroll
            for (int k2 = 0; k2 < 48; k2++) {       // 2 k per iter, k ascending
                const ulonglong2 v = x2[k2];
                zg = fma2(v.x, pk2(wg1r[2*k2+0], wg1r[2*k2+0]), zg);
                zg = fma2(v.y, pk2(wg1r[2*k2+1], wg1r[2*k2+1]), zg);
            }
            float zg0, zg1; upk2(zg, zg0, zg1);
            g1s2[h] = make_float2(xla_tanh(__fadd_rn(zg0, bg1r)),
                                  xla_tanh(__fadd_rn(zg1, bg1r)));
            BAR_A();          // g1 published -> dx chain starts
            __syncthreads();  // B
        }
    } else if (tid < 192) {
        // ===================== dx-warps (one column j, both elements packed) =====
        const int q = tid - 128;        // 0..63
        const int j = q;

        float wg2r[128];
        #pragma unroll
        for (int i = 0; i < 128; i++) wg2r[i] = Wg2[i * NXX + j];
        const float bg2r = bg2[j];

        const size_t u_base0 = (size_t)(b0 + 0) * TT * NUU + q;  // q<32 duty
        const size_t u_base1 = (size_t)(b0 + 1) * TT * NUU + q;

        float xr0 = x0[(size_t)(b0 + 0) * NXX + j];
        float xr1 = x0[(size_t)(b0 + 1) * NXX + j];
        float* oxp0 = out_x + (size_t)(b0 + 0) * TT * NXX + j;
        float* oxp1 = out_x + (size_t)(b0 + 1) * TT * NXX + j;

        __syncthreads();  // init visible

        const ulonglong2* g2 = (const ulonglong2*)&g1s2[0];

        #pragma unroll 1
        for (int t = 0; t < TT; t++) {
            const int pn = (t + 1) & 1;

            // ---- phase 1: record x_t, launch u(t+1) loads ----
            *oxp0 = xr0;  oxp0 += NXX;
            *oxp1 = xr1;  oxp1 += NXX;
            float un0 = 0.f, un1 = 0.f;
            if (q < 32) {
                int tn = (t + 1 < TT) ? (t + 1) : (TT - 1);
                un0 = u[u_base0 + (size_t)tn * NUU];
                un1 = u[u_base1 + (size_t)tn * NUU];
            }
            BAR_A();  // g1 ready

            // ---- phase 2: packed sequential 128-dot (ascending i) ----
            u64 dxa = pk2(0.f, 0.f);
            #pragma unroll
            for (int i2 = 0; i2 < 64; i2++) {
                const ulonglong2 v = g2[i2];
                dxa = fma2(v.x, pk2(wg2r[2*i2+0], wg2r[2*i2+0]), dxa);
                dxa = fma2(v.y, pk2(wg2r[2*i2+1], wg2r[2*i2+1]), dxa);
            }
            float dxa0, dxa1; upk2(dxa, dxa0, dxa1);
            // pinned HLO order: x_{t+1} = x + (dot + bg2)
            xr0 = __fadd_rn(xr0, __fadd_rn(dxa0, bg2r));
            xr1 = __fadd_rn(xr1, __fadd_rn(dxa1, bg2r));
            sxu2[pn][j] = make_float2(xr0, xr1);
            if (q < 32) sxu2[pn][64 + q] = make_float2(un0, un1);
            __syncthreads();  // B
        }
    } else if (tid < 320) {
        // ===================== h-warps (whole-step slack, B only) =================
        const int h = tid - 192;        // 0..127
        float wh1r[64];
        #pragma unroll
        for (int k = 0; k < 64; k++) wh1r[k] = Wh1[k * HH + h];
        const float bh1r = bh1[h];

        __syncthreads();  // init visible

        #pragma unroll 1
        for (int t = 0; t < TT; t++) {
            const int p = t & 1;
            const ulonglong2* x2 = (const ulonglong2*)&sxu2[p][0];

            u64 zh = pk2(0.f, 0.f);
            #pragma unroll
            for (int k2 = 0; k2 < 32; k2++) {
                const ulonglong2 v = x2[k2];
                zh = fma2(v.x, pk2(wh1r[2*k2+0], wh1r[2*k2+0]), zh);
                zh = fma2(v.y, pk2(wh1r[2*k2+1], wh1r[2*k2+1]), zh);
            }
            float zh0, zh1; upk2(zh, zh0, zh1);
            h1p2[p][h] = make_float2(xla_tanh(__fadd_rn(zh0, bh1r)),
                                     xla_tanh(__fadd_rn(zh1, bh1r)));
            __syncthreads();  // B: h1 committed with state
        }
    } else {
        // ===================== y threads (16 active, lagged, off the gate) ========
        const int oo = tid - 320;       // 0..31; active if oo<16

        float wh2r[128];
        const int oc = (oo < 16) ? oo : 0;
        #pragma unroll
        for (int i = 0; i < 128; i++) wh2r[i] = Wh2[i * NYY + oc];
        const float bh2r = bh2[oc];

        float* oyp0 = out_y + (size_t)(b0 + 0) * TT * NYY + oc;
        float* oyp1 = out_y + (size_t)(b0 + 1) * TT * NYY + oc;

        __syncthreads();  // init visible

        #pragma unroll 1
        for (int t = 0; t < TT; t++) {
            __syncthreads();  // B(t): h1p[t&1] ready
            const int pp = t & 1;
            const ulonglong2* h2 = (const ulonglong2*)&h1p2[pp][0];
            u64 ya = pk2(0.f, 0.f);
            #pragma unroll
            for (int i2 = 0; i2 < 64; i2++) {
                const ulonglong2 v = h2[i2];
                ya = fma2(v.x, pk2(wh2r[2*i2+0], wh2r[2*i2+0]), ya);
                ya = fma2(v.y, pk2(wh2r[2*i2+1], wh2r[2*i2+1]), ya);
            }
            float ya0, ya1; upk2(ya, ya0, ya1);
            if (oo < 16) {
                *oyp0 = __fadd_rn(ya0, bh2r);  oyp0 += NYY;
                *oyp1 = __fadd_rn(ya1, bh2r);  oyp1 += NYY;
            }
        }
    }
}

extern "C" void kernel_launch(void* const* d_in, const int* in_sizes, int n_in,
                              void* d_out, int out_size)
{
    const float* x0  = (const float*)d_in[0];
    const float* u   = (const float*)d_in[1];
    const float* Wg1 = (const float*)d_in[2];
    const float* bg1 = (const float*)d_in[3];
    const float* Wg2 = (const float*)d_in[4];
    const float* bg2 = (const float*)d_in[5];
    const float* Wh1 = (const float*)d_in[6];
    const float* bh1 = (const float*)d_in[7];
    const float* Wh2 = (const float*)d_in[8];
    const float* bh2 = (const float*)d_in[9];

    float* out_x = (float*)d_out;
    float* out_y = out_x + (size_t)BB * TT * NXX;

    ssm_kernel<<<BB / 2, 352>>>(x0, u, Wg1, bg1, Wg2, bg2,
                                Wh1, bh1, Wh2, bh2, out_x, out_y);
}